// round 13
// baseline (speedup 1.0000x reference)
#include <cuda_runtime.h>
#include <cuda_fp16.h>
#include <mma.h>
#include <cstdint>

using namespace nvcuda;

#define THREADS 512
#define TROWS 64          // tile rows
#define PST 136           // Pi smem stride (mult of 8 for wmma ldm)
#define XST 136           // X smem stride

// smem offsets in floats
#define OFF_PIHI 0
#define OFF_PILO (128 * PST)
#define OFF_XHI  (2 * 128 * PST)
#define OFF_XLO  (OFF_XHI + TROWS * XST)
#define OFF_RN   (OFF_XLO + TROWS * XST)
#define OFF_NQ   (OFF_RN + TROWS)
#define OFF_B    (OFF_NQ + TROWS)
#define OFF_C    (OFF_B + 16)
#define SMEM_FLOATS (OFF_C + 16)

__device__ __forceinline__ float to_tf32(float x) {
    float r; asm("cvt.rna.tf32.f32 %0, %1;" : "=f"(r) : "f"(x)); return r;
}

// Lloyd-Max bucketize (matches jnp.searchsorted side='left' over interior boundaries sB[1..15])
__device__ __forceinline__ int qidx(float v, const float* __restrict__ sB) {
    int i = (v > sB[8]) ? 8 : 0;
    i += (v > sB[i + 4]) ? 4 : 0;
    i += (v > sB[i + 2]) ? 2 : 0;
    i += (v > sB[i + 1]) ? 1 : 0;
    return i;
}

template <typename Frag>
__device__ __forceinline__ void cvt_frag(Frag& f) {
    #pragma unroll
    for (int i = 0; i < f.num_elements; ++i) f.x[i] = wmma::__float_to_tf32(f.x[i]);
}

__global__ __launch_bounds__(THREADS, 1)
void tq_kernel(const float* __restrict__ x, const float* __restrict__ Pi,
               const float* __restrict__ cen, const float* __restrict__ bnd,
               float* __restrict__ out, int n_tiles)
{
    extern __shared__ float sm[];
    float* PiHi = sm + OFF_PIHI;   // [128][PST] tf32(Pi[j][k])
    float* PiLo = sm + OFF_PILO;   // [128][PST] tf32(Pi - hi)
    float* Xhi  = sm + OFF_XHI;    // [64][XST]  x hi / rot / values-hi (reused)
    float* Xlo  = sm + OFF_XLO;    // [64][XST]  x lo / final recon (reused)
    float* sRn  = sm + OFF_RN;     // [64] 1/(norm+1e-8)
    float* sNq  = sm + OFF_NQ;     // [64] fp16-roundtripped norm
    float* sB   = sm + OFF_B;      // [16] boundaries
    float* sC   = sm + OFF_C;      // [16] centroids (tf32-rounded)

    const int tid  = threadIdx.x;
    const int w    = tid >> 5;     // warp 0..15
    const int lane = tid & 31;
    const int wr   = w >> 2;       // row group 0..3 -> rows wr*16
    const int wc   = w & 3;        // col group 0..3 -> cols wc*32 (+ t*16)

    // ---- stage Pi hi/lo once per block ----
    #pragma unroll
    for (int it = 0; it < 32; ++it) {
        int e = it * THREADS + tid;            // e = j*128 + k, 16384 total
        int j = e >> 7, k = e & 127;
        float v  = Pi[e];
        float hi = to_tf32(v);
        PiHi[j * PST + k] = hi;
        PiLo[j * PST + k] = to_tf32(v - hi);
    }
    if (tid < 16) sC[tid] = to_tf32(cen[tid]);
    if (tid < 16) sB[tid] = bnd[tid];
    __syncthreads();

    for (int tile = blockIdx.x; tile < n_tiles; tile += gridDim.x) {
        const float* gx   = x   + (size_t)tile * TROWS * 128;
        float*       gout = out + (size_t)tile * TROWS * 128;

        // ---- stage x tile split hi/lo + per-row norms (warp-uniform rows, shfl reduce) ----
        #pragma unroll
        for (int it = 0; it < 4; ++it) {
            int e = it * THREADS + tid;        // float4 index, 2048 total
            int r = e >> 5;                    // = it*16 + w (warp-uniform)
            int c4 = (e & 31) * 4;
            float4 v = reinterpret_cast<const float4*>(gx)[e];
            float h0 = to_tf32(v.x), h1 = to_tf32(v.y), h2 = to_tf32(v.z), h3 = to_tf32(v.w);
            *reinterpret_cast<float4*>(&Xhi[r * XST + c4]) = make_float4(h0, h1, h2, h3);
            *reinterpret_cast<float4*>(&Xlo[r * XST + c4]) =
                make_float4(to_tf32(v.x - h0), to_tf32(v.y - h1), to_tf32(v.z - h2), to_tf32(v.w - h3));
            float s = v.x * v.x + v.y * v.y + v.z * v.z + v.w * v.w;
            s += __shfl_xor_sync(0xffffffffu, s, 16);
            s += __shfl_xor_sync(0xffffffffu, s, 8);
            s += __shfl_xor_sync(0xffffffffu, s, 4);
            s += __shfl_xor_sync(0xffffffffu, s, 2);
            s += __shfl_xor_sync(0xffffffffu, s, 1);
            if (lane == 0) {
                float nrm = sqrtf(s);
                sRn[r] = 1.0f / (nrm + 1e-8f);
                sNq[r] = __half2float(__float2half_rn(nrm));
            }
        }
        __syncthreads();

        // ---- GEMM 1: rot = x @ Pi^T, tf32 3-term split ----
        {
            wmma::fragment<wmma::accumulator, 16, 16, 8, float> acc[2];
            wmma::fill_fragment(acc[0], 0.0f);
            wmma::fill_fragment(acc[1], 0.0f);
            wmma::fragment<wmma::matrix_a, 16, 16, 8, wmma::precision::tf32, wmma::row_major> aHi, aLo;
            wmma::fragment<wmma::matrix_b, 16, 16, 8, wmma::precision::tf32, wmma::col_major> bHi, bLo;

            #pragma unroll 4
            for (int kc = 0; kc < 16; ++kc) {
                wmma::load_matrix_sync(aHi, &Xhi[(wr * 16) * XST + kc * 8], XST);
                wmma::load_matrix_sync(aLo, &Xlo[(wr * 16) * XST + kc * 8], XST);
                cvt_frag(aHi); cvt_frag(aLo);
                #pragma unroll
                for (int t = 0; t < 2; ++t) {
                    int j0 = wc * 32 + t * 16;
                    wmma::load_matrix_sync(bHi, &PiHi[j0 * PST + kc * 8], PST);
                    wmma::load_matrix_sync(bLo, &PiLo[j0 * PST + kc * 8], PST);
                    cvt_frag(bHi); cvt_frag(bLo);
                    wmma::mma_sync(acc[t], aHi, bHi, acc[t]);
                    wmma::mma_sync(acc[t], aHi, bLo, acc[t]);
                    wmma::mma_sync(acc[t], aLo, bHi, acc[t]);
                }
            }
            __syncthreads();   // all warps done reading Xhi/Xlo before overwrite
            wmma::store_matrix_sync(&Xhi[(wr * 16) * XST + wc * 32],      acc[0], XST, wmma::mem_row_major);
            wmma::store_matrix_sync(&Xhi[(wr * 16) * XST + wc * 32 + 16], acc[1], XST, wmma::mem_row_major);
        }
        __syncthreads();

        // ---- quantize in place: Xhi <- tf32 centroid of bucket(rot * rn) ----
        #pragma unroll
        for (int it = 0; it < 16; ++it) {
            int e = it * THREADS + tid;        // 8192 elements
            int r = e >> 7, c = e & 127;
            float v = Xhi[r * XST + c] * sRn[r];
            Xhi[r * XST + c] = sC[qidx(v, sB)];
        }
        __syncthreads();

        // ---- GEMM 2: recon = v @ Pi, 2-term (vhi * (PiHi + PiLo)) ----
        {
            wmma::fragment<wmma::accumulator, 16, 16, 8, float> acc[2];
            wmma::fill_fragment(acc[0], 0.0f);
            wmma::fill_fragment(acc[1], 0.0f);
            wmma::fragment<wmma::matrix_a, 16, 16, 8, wmma::precision::tf32, wmma::row_major> aV;
            wmma::fragment<wmma::matrix_b, 16, 16, 8, wmma::precision::tf32, wmma::row_major> bHi, bLo;

            #pragma unroll 4
            for (int jc = 0; jc < 16; ++jc) {
                wmma::load_matrix_sync(aV, &Xhi[(wr * 16) * XST + jc * 8], XST);
                cvt_frag(aV);
                #pragma unroll
                for (int t = 0; t < 2; ++t) {
                    int k0 = wc * 32 + t * 16;
                    wmma::load_matrix_sync(bHi, &PiHi[(jc * 8) * PST + k0], PST);
                    wmma::load_matrix_sync(bLo, &PiLo[(jc * 8) * PST + k0], PST);
                    cvt_frag(bHi); cvt_frag(bLo);
                    wmma::mma_sync(acc[t], aV, bHi, acc[t]);
                    wmma::mma_sync(acc[t], aV, bLo, acc[t]);
                }
            }
            // store into Xlo (not read by GEMM2) — no block sync needed before
            wmma::store_matrix_sync(&Xlo[(wr * 16) * XST + wc * 32],      acc[0], XST, wmma::mem_row_major);
            wmma::store_matrix_sync(&Xlo[(wr * 16) * XST + wc * 32 + 16], acc[1], XST, wmma::mem_row_major);
        }
        __syncthreads();

        // ---- scale by fp16-roundtripped norm, coalesced store ----
        #pragma unroll
        for (int it = 0; it < 4; ++it) {
            int e = it * THREADS + tid;        // float4 index, 2048
            int r = e >> 5;
            int c4 = (e & 31) * 4;
            float nq = sNq[r];
            float4 v = *reinterpret_cast<const float4*>(&Xlo[r * XST + c4]);
            reinterpret_cast<float4*>(gout)[e] =
                make_float4(v.x * nq, v.y * nq, v.z * nq, v.w * nq);
        }
        __syncthreads();   // protect Xhi/Xlo/sRn/sNq before next tile's staging
    }
}

extern "C" void kernel_launch(void* const* d_in, const int* in_sizes, int n_in,
                              void* d_out, int out_size) {
    const float* x   = (const float*)d_in[0];
    const float* Pi  = (const float*)d_in[1];
    const float* cen = (const float*)d_in[2];
    const float* bnd = (const float*)d_in[3];
    float* out = (float*)d_out;

    int n_rows  = in_sizes[0] / 128;
    int n_tiles = n_rows / TROWS;

    int nsm = 148;
    cudaDeviceGetAttribute(&nsm, cudaDevAttrMultiProcessorCount, 0);
    if (nsm <= 0) nsm = 148;

    size_t smem_bytes = (size_t)SMEM_FLOATS * sizeof(float);
    cudaFuncSetAttribute(tq_kernel, cudaFuncAttributeMaxDynamicSharedMemorySize, (int)smem_bytes);

    tq_kernel<<<nsm, THREADS, smem_bytes>>>(x, Pi, cen, bnd, out, n_tiles);
}

// round 14
// speedup vs baseline: 1.8038x; 1.8038x over previous
#include <cuda_runtime.h>
#include <cuda_fp16.h>

#define STR 130            // smem row stride (floats): even (8B align), 2 mod 32 (2-way b-conflict)
#define THREADS 512

typedef unsigned long long ull;

__device__ __forceinline__ void fma2(ull &acc, ull a, ull b) {
    asm("fma.rn.f32x2 %0, %1, %2, %0;" : "+l"(acc) : "l"(a), "l"(b));
}
__device__ __forceinline__ float2 unpack2(ull v) {
    unsigned int lo, hi;
    asm("mov.b64 {%0, %1}, %2;" : "=r"(lo), "=r"(hi) : "l"(v));
    return make_float2(__uint_as_float(lo), __uint_as_float(hi));
}

// Lloyd-Max bucketize (matches jnp.searchsorted side='left' over interior boundaries sB[1..15])
__device__ __forceinline__ float quantize1(float v, const float* __restrict__ sB,
                                           const float* __restrict__ sC) {
    int i = (v > sB[8]) ? 8 : 0;
    i += (v > sB[i + 4]) ? 4 : 0;
    i += (v > sB[i + 2]) ? 2 : 0;
    i += (v > sB[i + 1]) ? 1 : 0;
    return sC[i];
}

__global__ __launch_bounds__(THREADS, 1)
void tq_kernel(const float* __restrict__ x, const float* __restrict__ Pi,
               const float* __restrict__ cen, const float* __restrict__ bnd,
               float* __restrict__ out, int n_tiles)
{
    extern __shared__ float sm[];
    float* sPi  = sm;                  // [128][STR] Pi[j][k]
    float* sPiT = sPi  + 128 * STR;    // [128][STR] PiT[k][j] = Pi[j][k]
    float* sX   = sPiT + 128 * STR;    // [128][STR] x tile / values tile (warp-private rows)
    float* sRn  = sX   + 128 * STR;    // [128]
    float* sNq  = sRn  + 128;          // [128]
    float* sB   = sNq  + 128;          // [16]
    float* sC   = sB   + 16;           // [16]

    const int tid  = threadIdx.x;
    const int w    = tid >> 5;         // warp 0..15 owns rows w*8..w*8+7 end-to-end
    const int lane = tid & 31;
    const int r0   = w * 8;

    // ---- stage Pi + PiT once per block ----
    #pragma unroll
    for (int it = 0; it < 8; ++it) {
        int idx = it * THREADS + tid;  // 4096 float4 reads
        int r = idx >> 5, c4 = (idx & 31) * 4;
        float4 v = reinterpret_cast<const float4*>(Pi)[idx];
        *reinterpret_cast<float2*>(&sPi[r * STR + c4])     = make_float2(v.x, v.y);
        *reinterpret_cast<float2*>(&sPi[r * STR + c4 + 2]) = make_float2(v.z, v.w);
        sPiT[(c4 + 0) * STR + r] = v.x;
        sPiT[(c4 + 1) * STR + r] = v.y;
        sPiT[(c4 + 2) * STR + r] = v.z;
        sPiT[(c4 + 3) * STR + r] = v.w;
    }
    if (tid < 16) sC[tid] = cen[tid];
    if (tid < 16) sB[tid] = bnd[tid];
    __syncthreads();

    for (int tile = blockIdx.x; tile < n_tiles; tile += gridDim.x) {
        const float* gx   = x   + (size_t)tile * 128 * 128;
        float*       gout = out + (size_t)tile * 128 * 128;

        // ---- stage own 8 rows + norms (warp-exclusive; no block syncs in loop) ----
        #pragma unroll
        for (int i = 0; i < 8; ++i) {
            int r = r0 + i;
            float4 v = *reinterpret_cast<const float4*>(gx + r * 128 + lane * 4);
            *reinterpret_cast<float2*>(&sX[r * STR + lane * 4])     = make_float2(v.x, v.y);
            *reinterpret_cast<float2*>(&sX[r * STR + lane * 4 + 2]) = make_float2(v.z, v.w);
            float s = v.x * v.x + v.y * v.y + v.z * v.z + v.w * v.w;
            s += __shfl_xor_sync(0xffffffffu, s, 16);
            s += __shfl_xor_sync(0xffffffffu, s, 8);
            s += __shfl_xor_sync(0xffffffffu, s, 4);
            s += __shfl_xor_sync(0xffffffffu, s, 2);
            s += __shfl_xor_sync(0xffffffffu, s, 1);
            if (lane == 0) {
                float nrm = sqrtf(s);
                sRn[r] = 1.0f / (nrm + 1e-8f);
                sNq[r] = __half2float(__float2half_rn(nrm));
            }
        }
        __syncwarp();

        // ---- GEMM 1: rot[r][j] = sum_k x[r][k] * Pi[j][k]
        //      a2 = x k-pairs (broadcast LDS.64), b2 = Pi[j] k-pairs (lane j = lane+32jj)
        //      acc = (even-k sum, odd-k sum) ----
        ull acc[8][4];
        #pragma unroll
        for (int i = 0; i < 8; ++i)
            #pragma unroll
            for (int jj = 0; jj < 4; ++jj) acc[i][jj] = 0ull;

        {
            const float* aP = sX  + r0 * STR;       // + i*STR + 2*kp
            const float* bP = sPi + lane * STR;     // + jj*32*STR + 2*kp
            #pragma unroll 8
            for (int kp = 0; kp < 64; ++kp) {
                ull b0 = *reinterpret_cast<const ull*>(bP + 2 * kp);
                ull b1 = *reinterpret_cast<const ull*>(bP + 32 * STR + 2 * kp);
                ull b2 = *reinterpret_cast<const ull*>(bP + 64 * STR + 2 * kp);
                ull b3 = *reinterpret_cast<const ull*>(bP + 96 * STR + 2 * kp);
                #pragma unroll
                for (int i = 0; i < 8; ++i) {
                    ull a = *reinterpret_cast<const ull*>(aP + i * STR + 2 * kp);
                    fma2(acc[i][0], a, b0);
                    fma2(acc[i][1], a, b1);
                    fma2(acc[i][2], a, b2);
                    fma2(acc[i][3], a, b3);
                }
            }
        }
        __syncwarp();

        // ---- quantize own rows -> values tile (in place) ----
        #pragma unroll
        for (int i = 0; i < 8; ++i) {
            int r = r0 + i;
            float rn = sRn[r];
            #pragma unroll
            for (int jj = 0; jj < 4; ++jj) {
                float2 p = unpack2(acc[i][jj]);
                float v = (p.x + p.y) * rn;
                sX[r * STR + lane + 32 * jj] = quantize1(v, sB, sC);
            }
        }
        __syncwarp();

        // ---- GEMM 2: recon[r][k] = sum_j values[r][j] * Pi[j][k]
        //      a2 = values j-pairs (broadcast), b2 = PiT[k] j-pairs (lane k = lane+32kk)
        //      acc = (even-j sum, odd-j sum) ----
        #pragma unroll
        for (int i = 0; i < 8; ++i)
            #pragma unroll
            for (int kk = 0; kk < 4; ++kk) acc[i][kk] = 0ull;

        {
            const float* aP = sX   + r0 * STR;      // + i*STR + 2*jp
            const float* bP = sPiT + lane * STR;    // + kk*32*STR + 2*jp
            #pragma unroll 8
            for (int jp = 0; jp < 64; ++jp) {
                ull b0 = *reinterpret_cast<const ull*>(bP + 2 * jp);
                ull b1 = *reinterpret_cast<const ull*>(bP + 32 * STR + 2 * jp);
                ull b2 = *reinterpret_cast<const ull*>(bP + 64 * STR + 2 * jp);
                ull b3 = *reinterpret_cast<const ull*>(bP + 96 * STR + 2 * jp);
                #pragma unroll
                for (int i = 0; i < 8; ++i) {
                    ull a = *reinterpret_cast<const ull*>(aP + i * STR + 2 * jp);
                    fma2(acc[i][0], a, b0);
                    fma2(acc[i][1], a, b1);
                    fma2(acc[i][2], a, b2);
                    fma2(acc[i][3], a, b3);
                }
            }
        }

        // ---- scale by fp16-roundtripped norm, store (coalesced STG.32 across lanes) ----
        #pragma unroll
        for (int i = 0; i < 8; ++i) {
            int r = r0 + i;
            float nq = sNq[r];
            #pragma unroll
            for (int kk = 0; kk < 4; ++kk) {
                float2 p = unpack2(acc[i][kk]);
                gout[r * 128 + lane + 32 * kk] = (p.x + p.y) * nq;
            }
        }
        __syncwarp();   // own-row sX reads done before next tile's staging overwrites
    }
}

extern "C" void kernel_launch(void* const* d_in, const int* in_sizes, int n_in,
                              void* d_out, int out_size) {
    const float* x   = (const float*)d_in[0];
    const float* Pi  = (const float*)d_in[1];
    const float* cen = (const float*)d_in[2];
    const float* bnd = (const float*)d_in[3];
    float* out = (float*)d_out;

    int n_rows  = in_sizes[0] / 128;
    int n_tiles = n_rows / 128;

    int nsm = 148;
    cudaDeviceGetAttribute(&nsm, cudaDevAttrMultiProcessorCount, 0);
    if (nsm <= 0) nsm = 148;

    size_t smem_bytes = (size_t)(3 * 128 * STR + 128 + 128 + 16 + 16) * sizeof(float);
    cudaFuncSetAttribute(tq_kernel, cudaFuncAttributeMaxDynamicSharedMemorySize, (int)smem_bytes);

    tq_kernel<<<nsm, THREADS, smem_bytes>>>(x, Pi, cen, bnd, out, n_tiles);
}